// round 8
// baseline (speedup 1.0000x reference)
#include <cuda_runtime.h>
#include <cstdint>

// ============================================================================
// LSTM seq2seq (B=32, T_IN=128, T_OUT=64, H=2048, IO=1) via mma.sync tf32.
// Base sm_100 ISA (no tcgen05/TMA). Per step:
//   gates[8192x32] = W[8192x2048] @ h[2048x32]   (tf32 MMA, fp32 accum)
// 64 CTAs x 128 thr; warp w = gate w of the CTA's 32 hidden units (m=32,n=32).
// A pre-permuted fragment-major -> direct LDG.128, 8-deep register pipeline.
// h staged fragment-major in global (parity double buffer), cp.async per chunk.
//
// R7 fix: A kb stride is 256 floats = 64 float4 (was wrongly 32 float4).
// ============================================================================

#define HID 2048
#define TIN 128
#define TOUT 64
#define NCTA 64
#define NKB 256
#define NCHUNK 16
#define KB_PER_CHUNK 16
#define ACTA_FLOATS 262144
#define HSTAGE_FLOATS 65536

// dynamic smem float offsets
#define SB_F(buf) ((buf) * 4096)
#define EX_F 8192
#define SHH_F 12416
#define SFC_F 13472
#define SX_F 13504
#define SMEM_BYTES 55296

// ---------------- device scratch --------------------------------------------
__device__ __align__(16) float g_Aenc[(size_t)NCTA * ACTA_FLOATS];  // 64 MB
__device__ __align__(16) float g_Adec[(size_t)NCTA * ACTA_FLOATS];  // 64 MB
__device__ __align__(16) float g_hstage[2][HSTAGE_FLOATS];
__device__ __align__(16) float g_c[HID * 32];
__device__ __align__(16) float g_ypart[TOUT * NCTA * 32];

// ---------------- single-source index maps ----------------------------------
__device__ __host__ __forceinline__ int frag_a_row(int lane, int j) {
    return (j >> 2) * 16 + (lane >> 2) + 8 * (j & 1);
}
__device__ __host__ __forceinline__ int frag_a_col(int lane, int j) {
    return (lane & 3) + 4 * ((j >> 1) & 1);
}
__device__ __forceinline__ int frag_d_row(int lane, int r) { return (lane >> 2) + 8 * (r >> 1); }
__device__ __forceinline__ int frag_d_col(int lane, int r) { return 2 * (lane & 3) + (r & 1); }
// staged-h fragment-major index for element h[k][n] (k=unit, n=batch)
__device__ __forceinline__ int hidx(int k, int n) {
    return (k >> 3) * 256 + (((n & 7) << 2) | (k & 3)) * 8 + (n >> 3) * 2 + ((k >> 2) & 1);
}

// ---------------- helpers ----------------------------------------------------
__device__ __forceinline__ float to_tf32(float v) {
    uint32_t r;
    asm("cvt.rna.tf32.f32 %0, %1;" : "=r"(r) : "f"(v));
    return __uint_as_float(r);
}
__device__ __forceinline__ void mma_tf32(float* d, const uint32_t* a, const uint32_t* b) {
    asm volatile(
        "mma.sync.aligned.m16n8k8.row.col.f32.tf32.tf32.f32 "
        "{%0,%1,%2,%3}, {%4,%5,%6,%7}, {%8,%9}, {%0,%1,%2,%3};"
        : "+f"(d[0]), "+f"(d[1]), "+f"(d[2]), "+f"(d[3])
        : "r"(a[0]), "r"(a[1]), "r"(a[2]), "r"(a[3]), "r"(b[0]), "r"(b[1]));
}
__device__ __forceinline__ void cp_async16(uint32_t saddr, const void* gaddr) {
    asm volatile("cp.async.cg.shared.global [%0], [%1], 16;" :: "r"(saddr), "l"(gaddr) : "memory");
}
__device__ __forceinline__ uint32_t smem_u32(const void* p) {
    uint32_t a;
    asm("{ .reg .u64 t; cvta.to.shared.u64 t, %1; cvt.u32.u64 %0, t; }" : "=r"(a) : "l"(p));
    return a;
}

// ---------------- prep: permute W_hh into fragment-major tf32 layout --------
__global__ void prep_kernel(const float* __restrict__ W, int which) {
    float* dst = which ? g_Adec : g_Aenc;
    size_t f = (size_t)blockIdx.x * 256 + threadIdx.x;
    int cta = (int)(f >> 18);
    int rem = (int)(f & 0x3FFFF);
    int w = rem >> 16;           // gate
    int kb = (rem >> 8) & 255;   // k-block of 8
    int li = rem & 255;
    int lane = li >> 3;
    int j = li & 7;
    int lr = frag_a_row(lane, j);
    int c = frag_a_col(lane, j);
    int grow = w * HID + cta * 32 + lr;
    int gcol = kb * 8 + c;
    dst[f] = to_tf32(W[(size_t)grow * HID + gcol]);
}

__global__ void init_kernel() {
    int i = blockIdx.x * blockDim.x + threadIdx.x;
    int n = gridDim.x * blockDim.x;
    for (int j = i; j < 2 * HSTAGE_FLOATS; j += n) ((float*)g_hstage)[j] = 0.f;
    for (int j = i; j < HID * 32; j += n) g_c[j] = 0.f;
}

__global__ void final_kernel(float* __restrict__ out, const float* __restrict__ fcb) {
    int i = blockIdx.x * blockDim.x + threadIdx.x;
    if (i < 32 * TOUT) {
        int b = i / TOUT, t = i % TOUT;
        float y = fcb[0];
        #pragma unroll 8
        for (int j = 0; j < NCTA; j++) y += g_ypart[(t * NCTA + j) * 32 + b];
        out[i] = y;
    }
}

// ---------------- per-step kernel -------------------------------------------
__global__ void __launch_bounds__(128, 1) step_kernel(
    const float* __restrict__ x,
    const float* __restrict__ Wih_e, const float* __restrict__ b_e,
    const float* __restrict__ Wih_d, const float* __restrict__ b_d,
    const float* __restrict__ fcW, const float* __restrict__ fcb,
    int step)
{
    extern __shared__ float smem[];
    const int tid = threadIdx.x;
    const int w = tid >> 5;
    const int lane = tid & 31;
    const int cta = blockIdx.x;

    const bool dec = (step >= TIN);
    const int p = step & 1;
    const float* Aperm = dec ? g_Adec : g_Aenc;
    const float* Wih = dec ? Wih_d : Wih_e;
    const float* bias = dec ? b_d : b_e;
    const float* Hs = g_hstage[p];

    if (tid < 32) {
        float v;
        if (!dec)             v = x[tid * TIN + step];
        else if (step == TIN) v = x[tid * TIN + (TIN - 1)];
        else {
            v = fcb[0];
            int d0 = step - TIN - 1;
            #pragma unroll 8
            for (int j = 0; j < NCTA; j++) v += g_ypart[(d0 * NCTA + j) * 32 + tid];
        }
        smem[SX_F + tid] = v;
    }
    if (dec && tid < 32) smem[SFC_F + tid] = fcW[cta * 32 + tid];

    // prologue: cp.async h-chunk 0
    uint32_t sb_base = smem_u32(smem);
    {
        uint32_t dstb = sb_base + SB_F(0) * 4;
        #pragma unroll
        for (int i = 0; i < 8; i++)
            cp_async16(dstb + (tid + i * 128) * 16, (const char*)Hs + (tid + i * 128) * 16);
        asm volatile("cp.async.commit_group;" ::: "memory");
    }

    const float* Aw = Aperm + ((size_t)(cta * 4 + w) << 16);
    const float4* Athr = (const float4*)(Aw + lane * 8);   // kb stride = 64 float4

    uint4 Ast[8][2];
    #pragma unroll
    for (int i = 0; i < 8; i++) {
        const float4* ap = Athr + i * 64;
        Ast[i][0] = *(const uint4*)(ap);
        Ast[i][1] = *(const uint4*)(ap + 1);
    }

    float d[2][4][4];
    #pragma unroll
    for (int mt = 0; mt < 2; mt++)
        #pragma unroll
        for (int nb = 0; nb < 4; nb++)
            #pragma unroll
            for (int r = 0; r < 4; r++) d[mt][nb][r] = 0.f;

    #pragma unroll 1
    for (int c = 0; c < NCHUNK; c++) {
        asm volatile("cp.async.wait_group 0;" ::: "memory");
        __syncthreads();
        if (c + 1 < NCHUNK) {
            uint32_t dstb = sb_base + SB_F((c + 1) & 1) * 4;
            const char* src = (const char*)(Hs + (c + 1) * 4096);
            #pragma unroll
            for (int i = 0; i < 8; i++)
                cp_async16(dstb + (tid + i * 128) * 16, src + (tid + i * 128) * 16);
            asm volatile("cp.async.commit_group;" ::: "memory");
        }
        const float* Bbuf = smem + SB_F(c & 1);
        #pragma unroll
        for (int kbi = 0; kbi < KB_PER_CHUNK; kbi++) {
            int kbg = c * KB_PER_CHUNK + kbi;
            uint32_t bf[8];
            #pragma unroll
            for (int nb = 0; nb < 4; nb++)
                #pragma unroll
                for (int cl = 0; cl < 2; cl++) {
                    int k_loc = kbi * 8 + (lane & 3) + 4 * cl;
                    int n = nb * 8 + (lane >> 2);
                    bf[nb * 2 + cl] = __float_as_uint(Bbuf[hidx(k_loc, n)]);
                }
            int s = kbg & 7;
            uint32_t a0[4] = {Ast[s][0].x, Ast[s][0].y, Ast[s][0].z, Ast[s][0].w};
            uint32_t a1[4] = {Ast[s][1].x, Ast[s][1].y, Ast[s][1].z, Ast[s][1].w};
            #pragma unroll
            for (int nb = 0; nb < 4; nb++) {
                mma_tf32(d[0][nb], a0, &bf[nb * 2]);
                mma_tf32(d[1][nb], a1, &bf[nb * 2]);
            }
            if (kbg + 8 < NKB) {
                const float4* ap = Athr + (kbg + 8) * 64;
                Ast[s][0] = *(const uint4*)(ap);
                Ast[s][1] = *(const uint4*)(ap + 1);
            }
        }
        __syncthreads();
    }

    // epilogue: gates -> smem exchange (+ x term + bias)
    #pragma unroll
    for (int mt = 0; mt < 2; mt++)
        #pragma unroll
        for (int r = 0; r < 4; r++) {
            int lr = mt * 16 + frag_d_row(lane, r);
            int grow = w * HID + cta * 32 + lr;
            float wv = Wih[grow];
            float bv = bias[grow];
            #pragma unroll
            for (int nb = 0; nb < 4; nb++) {
                int n = nb * 8 + frag_d_col(lane, r);
                smem[EX_F + w * 1056 + lr * 33 + n] = d[mt][nb][r] + wv * smem[SX_F + n] + bv;
            }
        }
    __syncthreads();

    // fused LSTM cell update
    {
        int lu = tid >> 2;
        int b0 = (tid & 3) * 8;
        int hu = cta * 32 + lu;
        float* hnext = g_hstage[p ^ 1];
        #pragma unroll
        for (int j = 0; j < 8; j++) {
            int b = b0 + j;
            float gi = smem[EX_F + 0 * 1056 + lu * 33 + b];
            float gf = smem[EX_F + 1 * 1056 + lu * 33 + b];
            float gg = smem[EX_F + 2 * 1056 + lu * 33 + b];
            float go = smem[EX_F + 3 * 1056 + lu * 33 + b];
            float si = 1.f / (1.f + expf(-gi));
            float sf = 1.f / (1.f + expf(-gf));
            float so = 1.f / (1.f + expf(-go));
            float cc = sf * g_c[hu * 32 + b] + si * tanhf(gg);
            g_c[hu * 32 + b] = cc;
            float hh = so * tanhf(cc);
            hnext[hidx(hu, b)] = to_tf32(hh);
            if (dec) smem[SHH_F + lu * 33 + b] = hh;
        }
    }
    __syncthreads();

    if (dec && tid < 32) {
        float y = 0.f;
        #pragma unroll
        for (int lu = 0; lu < 32; lu++)
            y += smem[SHH_F + lu * 33 + tid] * smem[SFC_F + lu];
        g_ypart[((step - TIN) * NCTA + cta) * 32 + tid] = y;
    }
}

// ---------------- host ------------------------------------------------------
extern "C" void kernel_launch(void* const* d_in, const int* in_sizes, int n_in,
                              void* d_out, int out_size) {
    const float *x, *eWih, *eWhh, *eb, *dWih, *dWhh, *db, *fcW, *fcb;
    if (in_sizes[0] == 4096) {
        // dict / signature order
        x    = (const float*)d_in[0];
        eWih = (const float*)d_in[2];
        eWhh = (const float*)d_in[3];
        eb   = (const float*)d_in[4];
        dWih = (const float*)d_in[5];
        dWhh = (const float*)d_in[6];
        db   = (const float*)d_in[7];
        fcW  = (const float*)d_in[8];
        fcb  = (const float*)d_in[9];
    } else {
        // key-sorted order
        dWhh = (const float*)d_in[0];
        dWih = (const float*)d_in[1];
        db   = (const float*)d_in[2];
        eWhh = (const float*)d_in[3];
        eWih = (const float*)d_in[4];
        eb   = (const float*)d_in[5];
        fcW  = (const float*)d_in[6];
        fcb  = (const float*)d_in[7];
        x    = (const float*)d_in[10];
    }
    float* out = (float*)d_out;

    cudaFuncSetAttribute(step_kernel, cudaFuncAttributeMaxDynamicSharedMemorySize, SMEM_BYTES);

    init_kernel<<<256, 256>>>();
    prep_kernel<<<65536, 256>>>(eWhh, 0);
    prep_kernel<<<65536, 256>>>(dWhh, 1);
    for (int s = 0; s < TIN + TOUT; s++)
        step_kernel<<<NCTA, 128, SMEM_BYTES>>>(x, eWih, eb, dWih, db, fcW, fcb, s);
    final_kernel<<<8, 256>>>(out, fcb);
}

// round 9
// speedup vs baseline: 1.0995x; 1.0995x over previous
#include <cuda_runtime.h>
#include <cstdint>

// ============================================================================
// LSTM seq2seq (B=32, T_IN=128, T_OUT=64, H=2048, IO=1) via mma.sync tf32.
//
// R8: 256 thr/CTA, 8 warps = (gate, k-half). Each warp: m32 x n32 x k1024,
// partial-sum reduction fused in epilogue. Vectorized LDS.128 B loads.
// ============================================================================

#define HID 2048
#define TIN 128
#define TOUT 64
#define NCTA 64
#define ACTA_FLOATS 262144
#define HSTAGE_FLOATS 65536

// dynamic smem float offsets
#define SB_F(i) ((i) * 4096)     // 4 chunk buffers (16 KB each)
#define EX_F 16384               // 4 gates x 32 units x 33
#define SHH_F 20608
#define SFC_F 21664
#define SX_F 21696
#define SMEM_BYTES 86912

// ---------------- device scratch --------------------------------------------
__device__ __align__(16) float g_Aenc[(size_t)NCTA * ACTA_FLOATS];  // 64 MB
__device__ __align__(16) float g_Adec[(size_t)NCTA * ACTA_FLOATS];  // 64 MB
__device__ __align__(16) float g_hstage[2][HSTAGE_FLOATS];
__device__ __align__(16) float g_c[HID * 32];
__device__ __align__(16) float g_ypart[TOUT * NCTA * 32];

// ---------------- index maps -------------------------------------------------
__device__ __host__ __forceinline__ int frag_a_row(int lane, int j) {
    return (j >> 2) * 16 + (lane >> 2) + 8 * (j & 1);
}
__device__ __host__ __forceinline__ int frag_a_col(int lane, int j) {
    return (lane & 3) + 4 * ((j >> 1) & 1);
}
__device__ __forceinline__ int frag_d_row(int lane, int r) { return (lane >> 2) + 8 * (r >> 1); }
__device__ __forceinline__ int frag_d_col(int lane, int r) { return 2 * (lane & 3) + (r & 1); }
// staged-h fragment-major index for h[k][n] (k=unit, n=batch)
__device__ __forceinline__ int hidx(int k, int n) {
    return (k >> 3) * 256 + (((n & 7) << 2) | (k & 3)) * 8 + (n >> 3) * 2 + ((k >> 2) & 1);
}

// ---------------- helpers ----------------------------------------------------
__device__ __forceinline__ float to_tf32(float v) {
    uint32_t r;
    asm("cvt.rna.tf32.f32 %0, %1;" : "=r"(r) : "f"(v));
    return __uint_as_float(r);
}
__device__ __forceinline__ void mma_tf32(float* d, const uint32_t* a, const uint32_t* b) {
    asm volatile(
        "mma.sync.aligned.m16n8k8.row.col.f32.tf32.tf32.f32 "
        "{%0,%1,%2,%3}, {%4,%5,%6,%7}, {%8,%9}, {%0,%1,%2,%3};"
        : "+f"(d[0]), "+f"(d[1]), "+f"(d[2]), "+f"(d[3])
        : "r"(a[0]), "r"(a[1]), "r"(a[2]), "r"(a[3]), "r"(b[0]), "r"(b[1]));
}
__device__ __forceinline__ void cp_async16(uint32_t saddr, const void* gaddr) {
    asm volatile("cp.async.cg.shared.global [%0], [%1], 16;" :: "r"(saddr), "l"(gaddr) : "memory");
}
__device__ __forceinline__ uint32_t smem_u32(const void* p) {
    uint32_t a;
    asm("{ .reg .u64 t; cvta.to.shared.u64 t, %1; cvt.u32.u64 %0, t; }" : "=r"(a) : "l"(p));
    return a;
}

// ---------------- prep: permute W_hh into fragment-major tf32 layout --------
__global__ void prep_kernel(const float* __restrict__ W, int which) {
    float* dst = which ? g_Adec : g_Aenc;
    size_t f = (size_t)blockIdx.x * 256 + threadIdx.x;
    int cta = (int)(f >> 18);
    int rem = (int)(f & 0x3FFFF);
    int w = rem >> 16;           // gate
    int kb = (rem >> 8) & 255;   // k-block of 8
    int li = rem & 255;
    int lane = li >> 3;
    int j = li & 7;
    int lr = frag_a_row(lane, j);
    int c = frag_a_col(lane, j);
    int grow = w * HID + cta * 32 + lr;
    int gcol = kb * 8 + c;
    dst[f] = to_tf32(W[(size_t)grow * HID + gcol]);
}

__global__ void init_kernel() {
    int i = blockIdx.x * blockDim.x + threadIdx.x;
    int n = gridDim.x * blockDim.x;
    for (int j = i; j < 2 * HSTAGE_FLOATS; j += n) ((float*)g_hstage)[j] = 0.f;
    for (int j = i; j < HID * 32; j += n) g_c[j] = 0.f;
}

__global__ void final_kernel(float* __restrict__ out, const float* __restrict__ fcb) {
    int i = blockIdx.x * blockDim.x + threadIdx.x;
    if (i < 32 * TOUT) {
        int b = i / TOUT, t = i % TOUT;
        float y = fcb[0];
        #pragma unroll 8
        for (int j = 0; j < NCTA; j++) y += g_ypart[(t * NCTA + j) * 32 + b];
        out[i] = y;
    }
}

// ---------------- per-step kernel -------------------------------------------
__global__ void __launch_bounds__(256, 1) step_kernel(
    const float* __restrict__ x,
    const float* __restrict__ Wih_e, const float* __restrict__ b_e,
    const float* __restrict__ Wih_d, const float* __restrict__ b_d,
    const float* __restrict__ fcW, const float* __restrict__ fcb,
    int step)
{
    extern __shared__ float smem[];
    const int tid = threadIdx.x;
    const int wid = tid >> 5;
    const int lane = tid & 31;
    const int g = wid & 3;        // gate
    const int kh = wid >> 2;      // k-half (0: kb 0..127, 1: kb 128..255)
    const int cta = blockIdx.x;

    const bool dec = (step >= TIN);
    const int p = step & 1;
    const float* Aperm = dec ? g_Adec : g_Aenc;
    const float* Wih = dec ? Wih_d : Wih_e;
    const float* bias = dec ? b_d : b_e;
    const float* Hs = g_hstage[p];

    if (tid < 32) {
        float v;
        if (!dec)             v = x[tid * TIN + step];
        else if (step == TIN) v = x[tid * TIN + (TIN - 1)];
        else {
            v = fcb[0];
            int d0 = step - TIN - 1;
            #pragma unroll 8
            for (int j = 0; j < NCTA; j++) v += g_ypart[(d0 * NCTA + j) * 32 + tid];
        }
        smem[SX_F + tid] = v;
    }
    if (dec && tid >= 32 && tid < 64) smem[SFC_F + tid - 32] = fcW[cta * 32 + (tid - 32)];

    // prologue: cp.async h-chunks 0 (half0) and 8 (half1)
    uint32_t sb_base = smem_u32(smem);
    {
        uint32_t d0b = sb_base + SB_F(0) * 4;
        uint32_t d1b = sb_base + SB_F(2) * 4;
        const char* s0 = (const char*)Hs;
        const char* s1 = (const char*)(Hs + 8 * 4096);
        #pragma unroll
        for (int i = 0; i < 4; i++) {
            cp_async16(d0b + (tid + i * 256) * 16, s0 + (tid + i * 256) * 16);
            cp_async16(d1b + (tid + i * 256) * 16, s1 + (tid + i * 256) * 16);
        }
        asm volatile("cp.async.commit_group;" ::: "memory");
    }

    // per-warp A base: (cta, gate) tile, k-half offset; kb stride = 64 float4
    const float* Aw = Aperm + ((size_t)(cta * 4 + g) << 16) + kh * 32768;
    const float4* Athr = (const float4*)(Aw + lane * 8);

    uint4 Ast[8][2];
    #pragma unroll
    for (int i = 0; i < 8; i++) {
        const float4* ap = Athr + i * 64;
        Ast[i][0] = *(const uint4*)(ap);
        Ast[i][1] = *(const uint4*)(ap + 1);
    }

    float d[2][4][4];
    #pragma unroll
    for (int mt = 0; mt < 2; mt++)
        #pragma unroll
        for (int nb = 0; nb < 4; nb++)
            #pragma unroll
            for (int r = 0; r < 4; r++) d[mt][nb][r] = 0.f;

    // mainloop: 8 chunk iterations; half kh consumes chunks kh*8 + c
    #pragma unroll 1
    for (int c = 0; c < 8; c++) {
        asm volatile("cp.async.wait_group 0;" ::: "memory");
        __syncthreads();
        if (c + 1 < 8) {
            uint32_t d0b = sb_base + SB_F((c + 1) & 1) * 4;
            uint32_t d1b = sb_base + SB_F(2 + ((c + 1) & 1)) * 4;
            const char* s0 = (const char*)(Hs + (c + 1) * 4096);
            const char* s1 = (const char*)(Hs + (c + 9) * 4096);
            #pragma unroll
            for (int i = 0; i < 4; i++) {
                cp_async16(d0b + (tid + i * 256) * 16, s0 + (tid + i * 256) * 16);
                cp_async16(d1b + (tid + i * 256) * 16, s1 + (tid + i * 256) * 16);
            }
            asm volatile("cp.async.commit_group;" ::: "memory");
        }
        const float* Bbuf = smem + SB_F(kh * 2 + (c & 1));
        #pragma unroll
        for (int kbi = 0; kbi < 16; kbi++) {
            int l = c * 16 + kbi;    // local kb index within this half (0..127)
            // B fragment: 2x LDS.128 (fold of hidx over fragment (k,n) pattern)
            uint4 B0 = *(const uint4*)(Bbuf + kbi * 256 + lane * 8);
            uint4 B1 = *(const uint4*)(Bbuf + kbi * 256 + lane * 8 + 4);
            uint32_t bf[8] = {B0.x, B0.y, B0.z, B0.w, B1.x, B1.y, B1.z, B1.w};
            int s = l & 7;
            uint32_t a0[4] = {Ast[s][0].x, Ast[s][0].y, Ast[s][0].z, Ast[s][0].w};
            uint32_t a1[4] = {Ast[s][1].x, Ast[s][1].y, Ast[s][1].z, Ast[s][1].w};
            #pragma unroll
            for (int nb = 0; nb < 4; nb++) {
                mma_tf32(d[0][nb], a0, &bf[nb * 2]);
                mma_tf32(d[1][nb], a1, &bf[nb * 2]);
            }
            if (l + 8 < 128) {
                const float4* ap = Athr + (l + 8) * 64;
                Ast[s][0] = *(const uint4*)(ap);
                Ast[s][1] = *(const uint4*)(ap + 1);
            }
        }
        __syncthreads();
    }

    // epilogue: half1 writes partials, half0 adds + bias + x term
    if (kh == 1) {
        #pragma unroll
        for (int mt = 0; mt < 2; mt++)
            #pragma unroll
            for (int r = 0; r < 4; r++) {
                int lr = mt * 16 + frag_d_row(lane, r);
                #pragma unroll
                for (int nb = 0; nb < 4; nb++) {
                    int n = nb * 8 + frag_d_col(lane, r);
                    smem[EX_F + g * 1056 + lr * 33 + n] = d[mt][nb][r];
                }
            }
    }
    __syncthreads();
    if (kh == 0) {
        #pragma unroll
        for (int mt = 0; mt < 2; mt++)
            #pragma unroll
            for (int r = 0; r < 4; r++) {
                int lr = mt * 16 + frag_d_row(lane, r);
                int grow = g * HID + cta * 32 + lr;
                float wv = Wih[grow];
                float bv = bias[grow];
                #pragma unroll
                for (int nb = 0; nb < 4; nb++) {
                    int n = nb * 8 + frag_d_col(lane, r);
                    smem[EX_F + g * 1056 + lr * 33 + n] +=
                        d[mt][nb][r] + wv * smem[SX_F + n] + bv;
                }
            }
    }
    __syncthreads();

    // fused LSTM cell update: 256 threads x 4 elements
    {
        int lu = tid >> 3;             // local unit 0..31
        int b0 = (tid & 7) * 4;
        int hu = cta * 32 + lu;
        float* hnext = g_hstage[p ^ 1];
        #pragma unroll
        for (int j = 0; j < 4; j++) {
            int b = b0 + j;
            float gi = smem[EX_F + 0 * 1056 + lu * 33 + b];
            float gf = smem[EX_F + 1 * 1056 + lu * 33 + b];
            float gg = smem[EX_F + 2 * 1056 + lu * 33 + b];
            float go = smem[EX_F + 3 * 1056 + lu * 33 + b];
            float si = 1.f / (1.f + expf(-gi));
            float sf = 1.f / (1.f + expf(-gf));
            float so = 1.f / (1.f + expf(-go));
            float cc = sf * g_c[hu * 32 + b] + si * tanhf(gg);
            g_c[hu * 32 + b] = cc;
            float hh = so * tanhf(cc);
            hnext[hidx(hu, b)] = to_tf32(hh);
            if (dec) smem[SHH_F + lu * 33 + b] = hh;
        }
    }
    __syncthreads();

    if (dec && tid < 32) {
        float y = 0.f;
        #pragma unroll
        for (int lu = 0; lu < 32; lu++)
            y += smem[SHH_F + lu * 33 + tid] * smem[SFC_F + lu];
        g_ypart[((step - TIN) * NCTA + cta) * 32 + tid] = y;
    }
}

// ---------------- host ------------------------------------------------------
extern "C" void kernel_launch(void* const* d_in, const int* in_sizes, int n_in,
                              void* d_out, int out_size) {
    const float *x, *eWih, *eWhh, *eb, *dWih, *dWhh, *db, *fcW, *fcb;
    if (in_sizes[0] == 4096) {
        x    = (const float*)d_in[0];
        eWih = (const float*)d_in[2];
        eWhh = (const float*)d_in[3];
        eb   = (const float*)d_in[4];
        dWih = (const float*)d_in[5];
        dWhh = (const float*)d_in[6];
        db   = (const float*)d_in[7];
        fcW  = (const float*)d_in[8];
        fcb  = (const float*)d_in[9];
    } else {
        dWhh = (const float*)d_in[0];
        dWih = (const float*)d_in[1];
        db   = (const float*)d_in[2];
        eWhh = (const float*)d_in[3];
        eWih = (const float*)d_in[4];
        eb   = (const float*)d_in[5];
        fcW  = (const float*)d_in[6];
        fcb  = (const float*)d_in[7];
        x    = (const float*)d_in[10];
    }
    float* out = (float*)d_out;

    cudaFuncSetAttribute(step_kernel, cudaFuncAttributeMaxDynamicSharedMemorySize, SMEM_BYTES);

    init_kernel<<<256, 256>>>();
    prep_kernel<<<65536, 256>>>(eWhh, 0);
    prep_kernel<<<65536, 256>>>(dWhh, 1);
    for (int s = 0; s < TIN + TOUT; s++)
        step_kernel<<<NCTA, 256, SMEM_BYTES>>>(x, eWih, eb, dWih, db, fcW, fcb, s);
    final_kernel<<<8, 256>>>(out, fcb);
}

// round 10
// speedup vs baseline: 1.5565x; 1.4157x over previous
#include <cuda_runtime.h>
#include <cstdint>

// ============================================================================
// LSTM seq2seq (B=32, T_IN=128, T_OUT=64, H=2048, IO=1) via mma.sync tf32.
//
// R9: 128 CTAs x 256 thr; CTA owns 16 hidden units. 8 warps = (gate, k-half),
// each m16 x n32 x k1024 = 512 MMAs. Halves per-SMSP MMA chain and doubles
// SM coverage vs R8.
// ============================================================================

#define HID 2048
#define TIN 128
#define TOUT 64
#define NCTA 128
#define ACTA_FLOATS 131072     // per CTA: 4 gates x 16 units x 2048 k
#define HSTAGE_FLOATS 65536

// dynamic smem float offsets
#define SB_F(i) ((i) * 4096)   // 4 chunk buffers (16 KB each)
#define EX_F 16384             // 4 gates x 16 units x 33
#define SHH_F 18496            // 16 x 33
#define SFC_F 19024            // 16
#define SX_F 19040             // 32
#define SRED_F 19072           // 8 x 32 reduction scratch
#define SMEM_BYTES 77312

// ---------------- device scratch --------------------------------------------
__device__ __align__(16) float g_Aenc[(size_t)NCTA * ACTA_FLOATS];  // 64 MB
__device__ __align__(16) float g_Adec[(size_t)NCTA * ACTA_FLOATS];  // 64 MB
__device__ __align__(16) float g_hstage[2][HSTAGE_FLOATS];
__device__ __align__(16) float g_c[HID * 32];
__device__ __align__(16) float g_ypart[TOUT * NCTA * 32];

// ---------------- index maps -------------------------------------------------
// m16n8k8 A fragment (m16): reg j 0..3 -> (row, col) within 16x8 tile
__device__ __forceinline__ int frag_a16_row(int lane, int j) {
    return (lane >> 2) + 8 * (j & 1);
}
__device__ __forceinline__ int frag_a16_col(int lane, int j) {
    return (lane & 3) + 4 * ((j >> 1) & 1);
}
__device__ __forceinline__ int frag_d_row(int lane, int r) { return (lane >> 2) + 8 * (r >> 1); }
__device__ __forceinline__ int frag_d_col(int lane, int r) { return 2 * (lane & 3) + (r & 1); }
// staged-h fragment-major index for h[k][n] (k=unit, n=batch)
__device__ __forceinline__ int hidx(int k, int n) {
    return (k >> 3) * 256 + (((n & 7) << 2) | (k & 3)) * 8 + (n >> 3) * 2 + ((k >> 2) & 1);
}

// ---------------- helpers ----------------------------------------------------
__device__ __forceinline__ float to_tf32(float v) {
    uint32_t r;
    asm("cvt.rna.tf32.f32 %0, %1;" : "=r"(r) : "f"(v));
    return __uint_as_float(r);
}
__device__ __forceinline__ void mma_tf32(float* d, const uint32_t* a, const uint32_t* b) {
    asm volatile(
        "mma.sync.aligned.m16n8k8.row.col.f32.tf32.tf32.f32 "
        "{%0,%1,%2,%3}, {%4,%5,%6,%7}, {%8,%9}, {%0,%1,%2,%3};"
        : "+f"(d[0]), "+f"(d[1]), "+f"(d[2]), "+f"(d[3])
        : "r"(a[0]), "r"(a[1]), "r"(a[2]), "r"(a[3]), "r"(b[0]), "r"(b[1]));
}
__device__ __forceinline__ void cp_async16(uint32_t saddr, const void* gaddr) {
    asm volatile("cp.async.cg.shared.global [%0], [%1], 16;" :: "r"(saddr), "l"(gaddr) : "memory");
}
__device__ __forceinline__ uint32_t smem_u32(const void* p) {
    uint32_t a;
    asm("{ .reg .u64 t; cvta.to.shared.u64 t, %1; cvt.u32.u64 %0, t; }" : "=r"(a) : "l"(p));
    return a;
}

// ---------------- prep: permute W_hh into fragment-major tf32 layout --------
// per (cta,gate): 256 kb x 32 lanes x 4 regs; cta owns units [cta*16, cta*16+16)
__global__ void prep_kernel(const float* __restrict__ W, int which) {
    float* dst = which ? g_Adec : g_Aenc;
    size_t f = (size_t)blockIdx.x * 256 + threadIdx.x;
    int cta = (int)(f >> 17);
    int rem = (int)(f & 0x1FFFF);
    int g = rem >> 15;            // gate
    int kb = (rem >> 7) & 255;    // k-block of 8
    int li = rem & 127;
    int lane = li >> 2;
    int j = li & 3;
    int lr = frag_a16_row(lane, j);      // 0..15
    int c = frag_a16_col(lane, j);       // 0..7
    int grow = g * HID + cta * 16 + lr;
    int gcol = kb * 8 + c;
    dst[f] = to_tf32(W[(size_t)grow * HID + gcol]);
}

__global__ void init_kernel() {
    int i = blockIdx.x * blockDim.x + threadIdx.x;
    int n = gridDim.x * blockDim.x;
    for (int j = i; j < 2 * HSTAGE_FLOATS; j += n) ((float*)g_hstage)[j] = 0.f;
    for (int j = i; j < HID * 32; j += n) g_c[j] = 0.f;
}

__global__ void final_kernel(float* __restrict__ out, const float* __restrict__ fcb) {
    int i = blockIdx.x * blockDim.x + threadIdx.x;
    if (i < 32 * TOUT) {
        int b = i / TOUT, t = i % TOUT;
        float y = fcb[0];
        #pragma unroll 8
        for (int j = 0; j < NCTA; j++) y += g_ypart[(t * NCTA + j) * 32 + b];
        out[i] = y;
    }
}

// ---------------- per-step kernel -------------------------------------------
__global__ void __launch_bounds__(256) step_kernel(
    const float* __restrict__ x,
    const float* __restrict__ Wih_e, const float* __restrict__ b_e,
    const float* __restrict__ Wih_d, const float* __restrict__ b_d,
    const float* __restrict__ fcW, const float* __restrict__ fcb,
    int step)
{
    extern __shared__ float smem[];
    const int tid = threadIdx.x;
    const int wid = tid >> 5;
    const int lane = tid & 31;
    const int g = wid & 3;        // gate
    const int kh = wid >> 2;      // k-half
    const int cta = blockIdx.x;

    const bool dec = (step >= TIN);
    const int p = step & 1;
    const float* Aperm = dec ? g_Adec : g_Aenc;
    const float* Wih = dec ? Wih_d : Wih_e;
    const float* bias = dec ? b_d : b_e;
    const float* Hs = g_hstage[p];

    // ---- input vector (two-phase 256-thread reduction for decoder) ----
    if (!dec) {
        if (tid < 32) smem[SX_F + tid] = x[tid * TIN + step];
    } else if (step == TIN) {
        if (tid < 32) smem[SX_F + tid] = x[tid * TIN + (TIN - 1)];
    } else {
        int pg = tid >> 5, b = tid & 31;
        int d0 = step - TIN - 1;
        float v = 0.f;
        #pragma unroll
        for (int j = 0; j < 16; j++)
            v += g_ypart[(d0 * NCTA + pg * 16 + j) * 32 + b];
        smem[SRED_F + pg * 32 + b] = v;
        __syncthreads();
        if (tid < 32) {
            float v2 = fcb[0];
            #pragma unroll
            for (int pgi = 0; pgi < 8; pgi++) v2 += smem[SRED_F + pgi * 32 + tid];
            smem[SX_F + tid] = v2;
        }
    }
    if (dec && tid >= 64 && tid < 80) smem[SFC_F + tid - 64] = fcW[cta * 16 + (tid - 64)];

    // ---- prologue: cp.async h-chunks 0 (half0) and 8 (half1) ----
    uint32_t sb_base = smem_u32(smem);
    {
        uint32_t d0b = sb_base + SB_F(0) * 4;
        uint32_t d1b = sb_base + SB_F(2) * 4;
        const char* s0 = (const char*)Hs;
        const char* s1 = (const char*)(Hs + 8 * 4096);
        #pragma unroll
        for (int i = 0; i < 4; i++) {
            cp_async16(d0b + (tid + i * 256) * 16, s0 + (tid + i * 256) * 16);
            cp_async16(d1b + (tid + i * 256) * 16, s1 + (tid + i * 256) * 16);
        }
        asm volatile("cp.async.commit_group;" ::: "memory");
    }

    // per-warp A base; kb stride = 128 floats = 32 float4
    const float* Aw = Aperm + ((size_t)(cta * 4 + g) << 15) + kh * 16384;
    const float4* Athr = (const float4*)(Aw + lane * 4);

    uint4 Ast[8];
    #pragma unroll
    for (int i = 0; i < 8; i++) Ast[i] = *(const uint4*)(Athr + i * 32);

    float d[4][4];
    #pragma unroll
    for (int nb = 0; nb < 4; nb++)
        #pragma unroll
        for (int r = 0; r < 4; r++) d[nb][r] = 0.f;

    // ---- mainloop: 8 chunk iterations; half kh consumes chunks kh*8 + c ----
    #pragma unroll 1
    for (int c = 0; c < 8; c++) {
        asm volatile("cp.async.wait_group 0;" ::: "memory");
        __syncthreads();
        if (c + 1 < 8) {
            uint32_t d0b = sb_base + SB_F((c + 1) & 1) * 4;
            uint32_t d1b = sb_base + SB_F(2 + ((c + 1) & 1)) * 4;
            const char* s0 = (const char*)(Hs + (c + 1) * 4096);
            const char* s1 = (const char*)(Hs + (c + 9) * 4096);
            #pragma unroll
            for (int i = 0; i < 4; i++) {
                cp_async16(d0b + (tid + i * 256) * 16, s0 + (tid + i * 256) * 16);
                cp_async16(d1b + (tid + i * 256) * 16, s1 + (tid + i * 256) * 16);
            }
            asm volatile("cp.async.commit_group;" ::: "memory");
        }
        const float* Bbuf = smem + SB_F(kh * 2 + (c & 1));
        #pragma unroll
        for (int kbi = 0; kbi < 16; kbi++) {
            int l = c * 16 + kbi;     // local kb within this half (0..127)
            uint4 B0 = *(const uint4*)(Bbuf + kbi * 256 + lane * 8);
            uint4 B1 = *(const uint4*)(Bbuf + kbi * 256 + lane * 8 + 4);
            uint32_t bf[8] = {B0.x, B0.y, B0.z, B0.w, B1.x, B1.y, B1.z, B1.w};
            int s = l & 7;
            uint32_t a0[4] = {Ast[s].x, Ast[s].y, Ast[s].z, Ast[s].w};
            #pragma unroll
            for (int nb = 0; nb < 4; nb++) mma_tf32(d[nb], a0, &bf[nb * 2]);
            if (l + 8 < 128) Ast[s] = *(const uint4*)(Athr + (l + 8) * 32);
        }
        __syncthreads();
    }

    // ---- epilogue: half1 writes partials, half0 adds + bias + x term ----
    if (kh == 1) {
        #pragma unroll
        for (int r = 0; r < 4; r++) {
            int lr = frag_d_row(lane, r);
            #pragma unroll
            for (int nb = 0; nb < 4; nb++) {
                int n = nb * 8 + frag_d_col(lane, r);
                smem[EX_F + g * 528 + lr * 33 + n] = d[nb][r];
            }
        }
    }
    __syncthreads();
    if (kh == 0) {
        #pragma unroll
        for (int r = 0; r < 4; r++) {
            int lr = frag_d_row(lane, r);
            int grow = g * HID + cta * 16 + lr;
            float wv = Wih[grow];
            float bv = bias[grow];
            #pragma unroll
            for (int nb = 0; nb < 4; nb++) {
                int n = nb * 8 + frag_d_col(lane, r);
                smem[EX_F + g * 528 + lr * 33 + n] += d[nb][r] + wv * smem[SX_F + n] + bv;
            }
        }
    }
    __syncthreads();

    // ---- fused LSTM cell update: 256 threads x 2 elements ----
    {
        int lu = tid >> 4;             // local unit 0..15
        int b0 = (tid & 15) * 2;
        int hu = cta * 16 + lu;
        float* hnext = g_hstage[p ^ 1];
        #pragma unroll
        for (int j = 0; j < 2; j++) {
            int b = b0 + j;
            float gi = smem[EX_F + 0 * 528 + lu * 33 + b];
            float gf = smem[EX_F + 1 * 528 + lu * 33 + b];
            float gg = smem[EX_F + 2 * 528 + lu * 33 + b];
            float go = smem[EX_F + 3 * 528 + lu * 33 + b];
            float si = 1.f / (1.f + expf(-gi));
            float sf = 1.f / (1.f + expf(-gf));
            float so = 1.f / (1.f + expf(-go));
            float cc = sf * g_c[hu * 32 + b] + si * tanhf(gg);
            g_c[hu * 32 + b] = cc;
            float hh = so * tanhf(cc);
            hnext[hidx(hu, b)] = to_tf32(hh);
            if (dec) smem[SHH_F + lu * 33 + b] = hh;
        }
    }
    __syncthreads();

    // ---- decoder fc partial over this CTA's 16 units ----
    if (dec && tid < 32) {
        float y = 0.f;
        #pragma unroll
        for (int lu = 0; lu < 16; lu++)
            y += smem[SHH_F + lu * 33 + tid] * smem[SFC_F + lu];
        g_ypart[((step - TIN) * NCTA + cta) * 32 + tid] = y;
    }
}

// ---------------- host ------------------------------------------------------
extern "C" void kernel_launch(void* const* d_in, const int* in_sizes, int n_in,
                              void* d_out, int out_size) {
    const float *x, *eWih, *eWhh, *eb, *dWih, *dWhh, *db, *fcW, *fcb;
    if (in_sizes[0] == 4096) {
        x    = (const float*)d_in[0];
        eWih = (const float*)d_in[2];
        eWhh = (const float*)d_in[3];
        eb   = (const float*)d_in[4];
        dWih = (const float*)d_in[5];
        dWhh = (const float*)d_in[6];
        db   = (const float*)d_in[7];
        fcW  = (const float*)d_in[8];
        fcb  = (const float*)d_in[9];
    } else {
        dWhh = (const float*)d_in[0];
        dWih = (const float*)d_in[1];
        db   = (const float*)d_in[2];
        eWhh = (const float*)d_in[3];
        eWih = (const float*)d_in[4];
        eb   = (const float*)d_in[5];
        fcW  = (const float*)d_in[6];
        fcb  = (const float*)d_in[7];
        x    = (const float*)d_in[10];
    }
    float* out = (float*)d_out;

    cudaFuncSetAttribute(step_kernel, cudaFuncAttributeMaxDynamicSharedMemorySize, SMEM_BYTES);

    init_kernel<<<256, 256>>>();
    prep_kernel<<<65536, 256>>>(eWhh, 0);
    prep_kernel<<<65536, 256>>>(dWhh, 1);
    for (int s = 0; s < TIN + TOUT; s++)
        step_kernel<<<NCTA, 256, SMEM_BYTES>>>(x, eWih, eb, dWih, db, fcW, fcb, s);
    final_kernel<<<8, 256>>>(out, fcb);
}